// round 9
// baseline (speedup 1.0000x reference)
#include <cuda_runtime.h>
#include <cuda_bf16.h>
#include <math.h>

// InnerCos: mean over rows of clamp(1 - cos_sim(x_i, centers[label_i]))
// x: [N, 256] f32, label: [N] i32, centers: [C, 256] f32 -> scalar f32

#define D_DIM 256
#define THREADS 256               // 8 warps
#define NW (THREADS / 32)
#define ROWS_PER_BLOCK 32         // grid 8192, tiny T_CTA -> tiny tail

// Pre-normalized centers (c / ||c||), C <= 256
__device__ float g_cnorm[256 * D_DIM];

// ---- Prologue: one warp per center, normalize into g_cnorm; also zero out ----
__global__ void center_norm_kernel(const float* __restrict__ cen, int C,
                                   float* __restrict__ out)
{
    const int c    = blockIdx.x;
    const int lane = threadIdx.x;
    if (c == 0 && lane == 0) *out = 0.0f;
    const float4* row = reinterpret_cast<const float4*>(cen + (size_t)c * D_DIM);
    float4 v0 = __ldg(row + lane);
    float4 v1 = __ldg(row + lane + 32);
    float s = v0.x*v0.x + v0.y*v0.y + v0.z*v0.z + v0.w*v0.w
            + v1.x*v1.x + v1.y*v1.y + v1.z*v1.z + v1.w*v1.w;
    #pragma unroll
    for (int o = 16; o > 0; o >>= 1)
        s += __shfl_xor_sync(0xffffffffu, s, o);
    float inv = rsqrtf(fmaxf(s, 1e-30f));
    v0.x *= inv; v0.y *= inv; v0.z *= inv; v0.w *= inv;
    v1.x *= inv; v1.y *= inv; v1.z *= inv; v1.w *= inv;
    float4* dst = reinterpret_cast<float4*>(g_cnorm + (size_t)c * D_DIM);
    dst[lane] = v0;
    dst[lane + 32] = v1;
}

// ---- Main: one 32-row group per CTA; 8 lanes/row; 8 batched LDG.128 ----
__global__ void __launch_bounds__(THREADS, 4)
inner_cos_kernel(const float* __restrict__ x,
                 const int* __restrict__ lab,
                 float* __restrict__ out,
                 int N, float invN)
{
    const int tid  = threadIdx.x;
    const int lane = tid & 31;
    const int warp = tid >> 5;
    const int sub  = lane >> 3;   // warp's row 0..3
    const int sl   = lane & 7;    // owns 8 float4 of the row

    const int r = blockIdx.x * ROWS_PER_BLOCK + warp * 4 + sub;
    const bool v = r < N;

    // label first (breaks dependency for center loads), then front-batch x
    const int lb = v ? __ldg(lab + r) : 0;

    const float4* xr = reinterpret_cast<const float4*>(
        x + (size_t)min(r, N - 1) * D_DIM);
    float4 a[8];
    #pragma unroll
    for (int j = 0; j < 8; ++j)
        a[j] = __ldg(xr + sl + 8 * j);       // 8 independent DRAM loads

    const float4* cr = reinterpret_cast<const float4*>(
        g_cnorm + (size_t)lb * D_DIM);

    float dot0 = 0.f, dot1 = 0.f, nx0 = 0.f, nx1 = 0.f;
    #pragma unroll
    for (int j = 0; j < 8; j += 2) {
        float4 c0 = cr[sl + 8 * j];          // L1-resident
        float4 c1 = cr[sl + 8 * (j + 1)];
        dot0 = fmaf(a[j].x, c0.x, fmaf(a[j].y, c0.y,
               fmaf(a[j].z, c0.z, fmaf(a[j].w, c0.w, dot0))));
        nx0  = fmaf(a[j].x, a[j].x, fmaf(a[j].y, a[j].y,
               fmaf(a[j].z, a[j].z, fmaf(a[j].w, a[j].w, nx0))));
        dot1 = fmaf(a[j+1].x, c1.x, fmaf(a[j+1].y, c1.y,
               fmaf(a[j+1].z, c1.z, fmaf(a[j+1].w, c1.w, dot1))));
        nx1  = fmaf(a[j+1].x, a[j+1].x, fmaf(a[j+1].y, a[j+1].y,
               fmaf(a[j+1].z, a[j+1].z, fmaf(a[j+1].w, a[j+1].w, nx1))));
    }
    float dot = dot0 + dot1;
    float nx2 = nx0 + nx1;

    #pragma unroll
    for (int o = 4; o > 0; o >>= 1) {        // reduce across the 8-lane group
        dot += __shfl_xor_sync(0xffffffffu, dot, o);
        nx2 += __shfl_xor_sync(0xffffffffu, nx2, o);
    }

    float acc = 0.0f;
    if (sl == 0 && v) {
        float cos = dot * rsqrtf(fmaxf(nx2, 1e-30f));
        acc = fminf(fmaxf(1.0f - cos, 1e-12f), 1e12f);
    }

    // ---- warp reduce (acc nonzero only on sl==0 lanes), block, one atomic ----
    #pragma unroll
    for (int o = 16; o > 0; o >>= 1)
        acc += __shfl_xor_sync(0xffffffffu, acc, o);

    __shared__ float wsum[NW];
    if (lane == 0) wsum[warp] = acc;
    __syncthreads();
    if (tid == 0) {
        float s = 0.0f;
        #pragma unroll
        for (int i = 0; i < NW; ++i) s += wsum[i];
        atomicAdd(out, s * invN);
    }
}

extern "C" void kernel_launch(void* const* d_in, const int* in_sizes, int n_in,
                              void* d_out, int out_size)
{
    const float* x   = (const float*)d_in[0];   // ref_emb [N, 256]
    const int*   lab = (const int*)d_in[1];     // ref_label [N]
    const float* cen = (const float*)d_in[2];   // centers [C, 256]
    float* out = (float*)d_out;

    const int N = in_sizes[1];
    const int C = in_sizes[2] / D_DIM;

    center_norm_kernel<<<C, 32>>>(cen, C, out);

    const int blocks = (N + ROWS_PER_BLOCK - 1) / ROWS_PER_BLOCK;
    inner_cos_kernel<<<blocks, THREADS>>>(x, lab, out, N, 1.0f / (float)N);
}

// round 10
// speedup vs baseline: 1.0374x; 1.0374x over previous
#include <cuda_runtime.h>
#include <cuda_bf16.h>
#include <math.h>

// InnerCos: mean over rows of clamp(1 - cos_sim(x_i, centers[label_i]))
// x: [N, 256] f32, label: [N] i32, centers: [C, 256] f32 -> scalar f32

#define D_DIM 256
#define THREADS 128               // 4 warps
#define NW (THREADS / 32)
#define GROUP_ROWS 16             // 4 warps * 4 rows
#define ROWS_PER_BLOCK 32         // 2 groups -> grid 8192

// Pre-normalized centers (c / ||c||), C <= 256
__device__ float g_cnorm[256 * D_DIM];

// ---- Prologue: one warp per center, normalize into g_cnorm; also zero out ----
__global__ void center_norm_kernel(const float* __restrict__ cen, int C,
                                   float* __restrict__ out)
{
    const int c    = blockIdx.x;
    const int lane = threadIdx.x;
    if (c == 0 && lane == 0) *out = 0.0f;
    const float4* row = reinterpret_cast<const float4*>(cen + (size_t)c * D_DIM);
    float4 v0 = __ldg(row + lane);
    float4 v1 = __ldg(row + lane + 32);
    float s = v0.x*v0.x + v0.y*v0.y + v0.z*v0.z + v0.w*v0.w
            + v1.x*v1.x + v1.y*v1.y + v1.z*v1.z + v1.w*v1.w;
    #pragma unroll
    for (int o = 16; o > 0; o >>= 1)
        s += __shfl_xor_sync(0xffffffffu, s, o);
    float inv = rsqrtf(fmaxf(s, 1e-30f));
    v0.x *= inv; v0.y *= inv; v0.z *= inv; v0.w *= inv;
    v1.x *= inv; v1.y *= inv; v1.z *= inv; v1.w *= inv;
    float4* dst = reinterpret_cast<float4*>(g_cnorm + (size_t)c * D_DIM);
    dst[lane] = v0;
    dst[lane + 32] = v1;
}

// per-row compute helper: dot/nx FMA chains on 8 float4 + 8-lane reduce
__device__ __forceinline__ float row_term(const float4* __restrict__ cr,
                                          const float4 a[8], int sl)
{
    float dot0 = 0.f, dot1 = 0.f, nx0 = 0.f, nx1 = 0.f;
    #pragma unroll
    for (int j = 0; j < 8; j += 2) {
        float4 c0 = cr[sl + 8 * j];          // L1-resident
        float4 c1 = cr[sl + 8 * (j + 1)];
        dot0 = fmaf(a[j].x, c0.x, fmaf(a[j].y, c0.y,
               fmaf(a[j].z, c0.z, fmaf(a[j].w, c0.w, dot0))));
        nx0  = fmaf(a[j].x, a[j].x, fmaf(a[j].y, a[j].y,
               fmaf(a[j].z, a[j].z, fmaf(a[j].w, a[j].w, nx0))));
        dot1 = fmaf(a[j+1].x, c1.x, fmaf(a[j+1].y, c1.y,
               fmaf(a[j+1].z, c1.z, fmaf(a[j+1].w, c1.w, dot1))));
        nx1  = fmaf(a[j+1].x, a[j+1].x, fmaf(a[j+1].y, a[j+1].y,
               fmaf(a[j+1].z, a[j+1].z, fmaf(a[j+1].w, a[j+1].w, nx1))));
    }
    float dot = dot0 + dot1;
    float nx2 = nx0 + nx1;
    #pragma unroll
    for (int o = 4; o > 0; o >>= 1) {
        dot += __shfl_xor_sync(0xffffffffu, dot, o);
        nx2 += __shfl_xor_sync(0xffffffffu, nx2, o);
    }
    float cos = dot * rsqrtf(fmaxf(nx2, 1e-30f));
    return fminf(fmaxf(1.0f - cos, 1e-12f), 1e12f);
}

// ---- Main: 128 threads, 2 explicit ping-pong groups, double-buffered ----
__global__ void __launch_bounds__(THREADS, 6)
inner_cos_kernel(const float* __restrict__ x,
                 const int* __restrict__ lab,
                 float* __restrict__ out,
                 int N, float invN)
{
    const int tid  = threadIdx.x;
    const int lane = tid & 31;
    const int warp = tid >> 5;
    const int sub  = lane >> 3;   // warp's row 0..3 within a group
    const int sl   = lane & 7;    // owns 8 float4 of the row

    const int rbase = blockIdx.x * ROWS_PER_BLOCK + warp * 4 + sub;
    const int rA = rbase;                    // group 0 row
    const int rB = rbase + GROUP_ROWS;       // group 1 row
    const bool vA = rA < N;
    const bool vB = rB < N;

    float acc = 0.0f;

    // ---- group 0 loads (labels first, then 8 batched LDG.128) ----
    const int lbA = vA ? __ldg(lab + rA) : 0;
    const float4* xrA = reinterpret_cast<const float4*>(
        x + (size_t)min(rA, N - 1) * D_DIM);
    float4 a[8];
    #pragma unroll
    for (int j = 0; j < 8; ++j)
        a[j] = __ldg(xrA + sl + 8 * j);

    // ---- group 1 loads issued BEFORE group 0 compute (pipeline) ----
    const int lbB = vB ? __ldg(lab + rB) : 0;
    const float4* xrB = reinterpret_cast<const float4*>(
        x + (size_t)min(rB, N - 1) * D_DIM);
    float4 b[8];
    #pragma unroll
    for (int j = 0; j < 8; ++j)
        b[j] = __ldg(xrB + sl + 8 * j);

    // ---- compute group 0 ----
    {
        const float4* cr = reinterpret_cast<const float4*>(
            g_cnorm + (size_t)lbA * D_DIM);
        float t = row_term(cr, a, sl);
        if (sl == 0 && vA) acc += t;
    }

    // ---- compute group 1 ----
    {
        const float4* cr = reinterpret_cast<const float4*>(
            g_cnorm + (size_t)lbB * D_DIM);
        float t = row_term(cr, b, sl);
        if (sl == 0 && vB) acc += t;
    }

    // ---- warp reduce (acc nonzero only on sl==0 lanes), block, one atomic ----
    #pragma unroll
    for (int o = 16; o > 0; o >>= 1)
        acc += __shfl_xor_sync(0xffffffffu, acc, o);

    __shared__ float wsum[NW];
    if (lane == 0) wsum[warp] = acc;
    __syncthreads();
    if (tid == 0) {
        float s = 0.0f;
        #pragma unroll
        for (int i = 0; i < NW; ++i) s += wsum[i];
        atomicAdd(out, s * invN);
    }
}

extern "C" void kernel_launch(void* const* d_in, const int* in_sizes, int n_in,
                              void* d_out, int out_size)
{
    const float* x   = (const float*)d_in[0];   // ref_emb [N, 256]
    const int*   lab = (const int*)d_in[1];     // ref_label [N]
    const float* cen = (const float*)d_in[2];   // centers [C, 256]
    float* out = (float*)d_out;

    const int N = in_sizes[1];
    const int C = in_sizes[2] / D_DIM;

    center_norm_kernel<<<C, 32>>>(cen, C, out);

    const int blocks = (N + ROWS_PER_BLOCK - 1) / ROWS_PER_BLOCK;
    inner_cos_kernel<<<blocks, THREADS>>>(x, lab, out, N, 1.0f / (float)N);
}

// round 11
// speedup vs baseline: 1.1496x; 1.1081x over previous
#include <cuda_runtime.h>
#include <cuda_bf16.h>
#include <math.h>

// InnerCos: mean over rows of clamp(1 - cos_sim(x_i, centers[label_i]))
// x: [N, 256] f32, label: [N] i32, centers: [C, 256] f32 -> scalar f32
// Single kernel: center norms computed inline (center row is loaded anyway).

#define D_DIM 256
#define THREADS 256               // 8 warps
#define NW (THREADS / 32)
#define GROUPS 2                  // compile-time static; 32 rows per group
#define ROWS_PER_BLOCK (GROUPS * 32)   // 64 -> grid 4096 (~9 balanced waves)

// ---- Main: 8 lanes/row, 4 rows/warp, register double-buffer, static unroll ----
__global__ void __launch_bounds__(THREADS, 3)
inner_cos_kernel(const float* __restrict__ x,
                 const int* __restrict__ lab,
                 const float* __restrict__ cen,
                 float* __restrict__ out,
                 int N, float invN)
{
    const int tid  = threadIdx.x;
    const int lane = tid & 31;
    const int warp = tid >> 5;
    const int sub  = lane >> 3;   // warp's row 0..3 within a group
    const int sl   = lane & 7;    // owns 8 float4 of the row

    // row for iteration it: rbase + it * 32
    const int rbase = blockIdx.x * ROWS_PER_BLOCK + warp * 4 + sub;

    float acc = 0.0f;

    // ---- pipeline prologue: group 0 loads ----
    int   r0  = rbase;
    int   lb  = (r0 < N) ? __ldg(lab + r0) : 0;
    float4 a[8];
    {
        const float4* xr = reinterpret_cast<const float4*>(
            x + (size_t)min(r0, N - 1) * D_DIM);
        #pragma unroll
        for (int j = 0; j < 8; ++j)
            a[j] = __ldg(xr + sl + 8 * j);
    }

    #pragma unroll
    for (int it = 0; it < GROUPS; ++it) {
        const bool v      = (rbase + it * 32) < N;
        const int  lb_cur = lb;

        // ---- issue NEXT group's loads first (keep DRAM queue full) ----
        float4 b[8];
        if (it + 1 < GROUPS) {
            const int rn = rbase + (it + 1) * 32;
            lb = (rn < N) ? __ldg(lab + rn) : 0;
            const float4* xn = reinterpret_cast<const float4*>(
                x + (size_t)min(rn, N - 1) * D_DIM);
            #pragma unroll
            for (int j = 0; j < 8; ++j)
                b[j] = __ldg(xn + sl + 8 * j);
        }

        // ---- compute on CURRENT group: dot, ||x||^2, ||c||^2 inline ----
        const float4* cr = reinterpret_cast<const float4*>(
            cen + (size_t)lb_cur * D_DIM);

        float dot0 = 0.f, dot1 = 0.f, nx0 = 0.f, nx1 = 0.f, nc0 = 0.f, nc1 = 0.f;
        #pragma unroll
        for (int j = 0; j < 8; j += 2) {
            float4 c0 = __ldg(cr + sl + 8 * j);        // L1-resident
            float4 c1 = __ldg(cr + sl + 8 * (j + 1));
            dot0 = fmaf(a[j].x, c0.x, fmaf(a[j].y, c0.y,
                   fmaf(a[j].z, c0.z, fmaf(a[j].w, c0.w, dot0))));
            nx0  = fmaf(a[j].x, a[j].x, fmaf(a[j].y, a[j].y,
                   fmaf(a[j].z, a[j].z, fmaf(a[j].w, a[j].w, nx0))));
            nc0  = fmaf(c0.x, c0.x, fmaf(c0.y, c0.y,
                   fmaf(c0.z, c0.z, fmaf(c0.w, c0.w, nc0))));
            dot1 = fmaf(a[j+1].x, c1.x, fmaf(a[j+1].y, c1.y,
                   fmaf(a[j+1].z, c1.z, fmaf(a[j+1].w, c1.w, dot1))));
            nx1  = fmaf(a[j+1].x, a[j+1].x, fmaf(a[j+1].y, a[j+1].y,
                   fmaf(a[j+1].z, a[j+1].z, fmaf(a[j+1].w, a[j+1].w, nx1))));
            nc1  = fmaf(c1.x, c1.x, fmaf(c1.y, c1.y,
                   fmaf(c1.z, c1.z, fmaf(c1.w, c1.w, nc1))));
        }
        float dot = dot0 + dot1;
        float nx2 = nx0 + nx1;
        float nc2 = nc0 + nc1;

        #pragma unroll
        for (int o = 4; o > 0; o >>= 1) {      // reduce across the 8-lane group
            dot += __shfl_xor_sync(0xffffffffu, dot, o);
            nx2 += __shfl_xor_sync(0xffffffffu, nx2, o);
            nc2 += __shfl_xor_sync(0xffffffffu, nc2, o);
        }

        if (sl == 0 && v) {
            // cos = dot / max(||x||*||c||, 1e-8)  ==  dot * rsqrt(max(nx2*nc2, 1e-16))
            float cos = dot * rsqrtf(fmaxf(nx2 * nc2, 1e-16f));
            acc += fminf(fmaxf(1.0f - cos, 1e-12f), 1e12f);
        }

        // ---- rotate pipeline ----
        if (it + 1 < GROUPS) {
            #pragma unroll
            for (int j = 0; j < 8; ++j) a[j] = b[j];
        }
    }

    // ---- warp reduce (acc nonzero only on sl==0 lanes), block, one atomic ----
    #pragma unroll
    for (int o = 16; o > 0; o >>= 1)
        acc += __shfl_xor_sync(0xffffffffu, acc, o);

    __shared__ float wsum[NW];
    if (lane == 0) wsum[warp] = acc;
    __syncthreads();
    if (tid == 0) {
        float s = 0.0f;
        #pragma unroll
        for (int i = 0; i < NW; ++i) s += wsum[i];
        atomicAdd(out, s * invN);
    }
}

extern "C" void kernel_launch(void* const* d_in, const int* in_sizes, int n_in,
                              void* d_out, int out_size)
{
    const float* x   = (const float*)d_in[0];   // ref_emb [N, 256]
    const int*   lab = (const int*)d_in[1];     // ref_label [N]
    const float* cen = (const float*)d_in[2];   // centers [C, 256]
    float* out = (float*)d_out;

    const int N = in_sizes[1];

    cudaMemsetAsync(d_out, 0, sizeof(float), 0);

    const int blocks = (N + ROWS_PER_BLOCK - 1) / ROWS_PER_BLOCK;
    inner_cos_kernel<<<blocks, THREADS>>>(x, lab, cen, out, N, 1.0f / (float)N);
}